// round 8
// baseline (speedup 1.0000x reference)
#include <cuda_runtime.h>
#include <cuda_bf16.h>

#define TT 256
#define BB 16
#define SS 1024
#define VV 32000
#define MM 4096
#define RCTAS 128

typedef unsigned long long ull;

// ---------------- device statics (~16.4 MB) ---------------------------------
__device__ float  g_H2[(size_t)MM*SS];    // layer-1 hidden states (also X early)
__device__ float2 g_hf [SS*8];            // canonical h   fp32 pairs [bp][k]
__device__ float2 g_rhf[SS*8];            // r*h           fp32 pairs [bp][k]
__device__ unsigned g_cnt, g_gen;

// ---------------- fp32x2 helpers --------------------------------------------
__device__ __forceinline__ ull pk2(float lo, float hi){
  ull r; asm("mov.b64 %0,{%1,%2};" : "=l"(r) : "f"(lo), "f"(hi)); return r;
}
__device__ __forceinline__ void unpk(ull v, float& lo, float& hi){
  asm("mov.b64 {%0,%1},%2;" : "=f"(lo), "=f"(hi) : "l"(v));
}
__device__ __forceinline__ void ffma2(ull& c, ull a, ull b){
  asm("fma.rn.f32x2 %0,%1,%2,%0;" : "+l"(c) : "l"(a), "l"(b));
}
__device__ __forceinline__ ull redd(ull v){
  #pragma unroll
  for (int off = 16; off; off >>= 1){
    ull o = __shfl_xor_sync(0xffffffffu, v, off);
    asm("add.rn.f32x2 %0,%0,%1;" : "+l"(v) : "l"(o));
  }
  return v;
}
__device__ __forceinline__ float sigf(float x){ return 1.f/(1.f+__expf(-x)); }

// ---------------- grid barrier (release/acquire, 128 co-resident CTAs) ------
__device__ __forceinline__ void gsync(){
  __syncthreads();
  if (threadIdx.x == 0){
    unsigned g0, old;
    asm volatile("ld.acquire.gpu.u32 %0,[%1];" : "=r"(g0) : "l"(&g_gen));
    asm volatile("atom.add.release.gpu.u32 %0,[%1],%2;" : "=r"(old) : "l"(&g_cnt), "r"(1u));
    if (old == RCTAS - 1u){
      asm volatile("st.relaxed.gpu.u32 [%0],%1;" :: "l"(&g_cnt), "r"(0u));
      unsigned g1 = g0 + 1u;
      asm volatile("st.release.gpu.u32 [%0],%1;" :: "l"(&g_gen), "r"(g1));
    } else {
      unsigned cur;
      do {
        __nanosleep(32);
        asm volatile("ld.acquire.gpu.u32 %0,[%1];" : "=r"(cur) : "l"(&g_gen));
      } while (cur == g0);
    }
  }
  __syncthreads();
}

// ---------------- embedding gather: X[m=t*16+b] = emb[x[b][t]] --------------
__global__ void embed_k(const int* __restrict__ x, const float* __restrict__ emb,
                        float* __restrict__ X){
  int m = blockIdx.x;
  int t = m >> 4, b = m & 15;
  int tok = x[b*TT + t];
  float4 v = *(const float4*)(emb + (size_t)tok*SS + threadIdx.x*4);
  *(float4*)(X + (size_t)m*SS + threadIdx.x*4) = v;
}

__global__ void zero_h_k(){
  int i = blockIdx.x*256 + threadIdx.x;   // 8192 total
  g_hf[i] = make_float2(0.f, 0.f);
}

// ---------------- fp32x2 GEMM: C[M,N] = A[M,K]@B[K,N] + bias ----------------
// BM=128 BN=64 BK=16, 256 threads, 8m x 4n per thread via FFMA2 on m-pairs.
// mode: 0 = fp32 out, 1 = fp32 out + [T,B]->[B,T] row remap
__global__ __launch_bounds__(256) void gemm_k(
    const float* __restrict__ A, const float* __restrict__ Bm,
    const float* __restrict__ bias, float* __restrict__ C,
    int K, int N, int mode)
{
  __shared__ __align__(16) float Ast[16*132];
  __shared__ __align__(16) float Bs [16*68];
  int tid = threadIdx.x;
  int tx = tid & 15, ty = tid >> 4;
  int m0 = blockIdx.x * 128, n0 = blockIdx.y * 64;
  int br = tid >> 4, bq = tid & 15;

  ull acc[4][4];
  #pragma unroll
  for (int p = 0; p < 4; p++)
    #pragma unroll
    for (int c = 0; c < 4; c++) acc[p][c] = 0ull;

  for (int kt = 0; kt < K; kt += 16){
    #pragma unroll
    for (int s = 0; s < 2; s++){
      int idx = tid + s*256;
      int ar = idx >> 2, aq = idx & 3;
      float4 av = *(const float4*)(A + (size_t)(m0+ar)*K + kt + aq*4);
      Ast[(aq*4+0)*132 + ar] = av.x;
      Ast[(aq*4+1)*132 + ar] = av.y;
      Ast[(aq*4+2)*132 + ar] = av.z;
      Ast[(aq*4+3)*132 + ar] = av.w;
    }
    float4 bv = *(const float4*)(Bm + (size_t)(kt+br)*N + n0 + bq*4);
    *(float4*)(Bs + br*68 + bq*4) = bv;
    __syncthreads();
    #pragma unroll
    for (int k = 0; k < 16; k++){
      ulonglong2 a0 = *(const ulonglong2*)(Ast + k*132 + ty*8);
      ulonglong2 a1 = *(const ulonglong2*)(Ast + k*132 + ty*8 + 4);
      float4 b4 = *(const float4*)(Bs + k*68 + tx*4);
      ull bb;
      bb = pk2(b4.x,b4.x);
      ffma2(acc[0][0],a0.x,bb); ffma2(acc[1][0],a0.y,bb);
      ffma2(acc[2][0],a1.x,bb); ffma2(acc[3][0],a1.y,bb);
      bb = pk2(b4.y,b4.y);
      ffma2(acc[0][1],a0.x,bb); ffma2(acc[1][1],a0.y,bb);
      ffma2(acc[2][1],a1.x,bb); ffma2(acc[3][1],a1.y,bb);
      bb = pk2(b4.z,b4.z);
      ffma2(acc[0][2],a0.x,bb); ffma2(acc[1][2],a0.y,bb);
      ffma2(acc[2][2],a1.x,bb); ffma2(acc[3][2],a1.y,bb);
      bb = pk2(b4.w,b4.w);
      ffma2(acc[0][3],a0.x,bb); ffma2(acc[1][3],a0.y,bb);
      ffma2(acc[2][3],a1.x,bb); ffma2(acc[3][3],a1.y,bb);
    }
    __syncthreads();
  }

  float4 bias4 = *(const float4*)(bias + n0 + tx*4);
  float bb4[4] = {bias4.x, bias4.y, bias4.z, bias4.w};
  #pragma unroll
  for (int p = 0; p < 4; p++){
    float lo[4], hi[4];
    #pragma unroll
    for (int c = 0; c < 4; c++){
      float l, h; unpk(acc[p][c], l, h);
      lo[c] = l + bb4[c]; hi[c] = h + bb4[c];
    }
    int ma = m0 + ty*8 + 2*p;
    int mb = ma + 1;
    int ra = (mode == 1) ? ((ma & 15)*TT + (ma >> 4)) : ma;
    int rb = (mode == 1) ? ((mb & 15)*TT + (mb >> 4)) : mb;
    *(float4*)(C + (size_t)ra*N + n0 + tx*4) = make_float4(lo[0],lo[1],lo[2],lo[3]);
    *(float4*)(C + (size_t)rb*N + n0 + tx*4) = make_float4(hi[0],hi[1],hi[2],hi[3]);
  }
}

// ---------------- persistent GRU layer recurrence (all fp32) ----------------
// 128 CTAs x 256 thr. CTA c owns state cols [c*8, c*8+8). W_h slices live in
// SMEM for all 256 steps. Phase1: warp (gate=w&1, cpair=w>>1) -> z/r for 2
// cols. Phase2: warp w -> n for col c*8+w, then h update.
// SMEM: 96KB weights + 64KB h pairs + 1.5KB = 161.5KB
#define GRU_DSMEM (98304 + 65536 + 512 + 1024)
__global__ __launch_bounds__(256, 1) void gru_layer_k(
    const float* __restrict__ Gz, const float* __restrict__ Gr,
    const float* __restrict__ Gn,
    const float* __restrict__ Whz, const float* __restrict__ Whr,
    const float* __restrict__ Whn, float* __restrict__ Hout)
{
  extern __shared__ __align__(16) float dynf[];
  float*  Ws  = dynf;                        // 3*8*1024 f32 [g][jl][k]
  ull*    hs  = (ull*)(dynf + 24576);        // f32x2 pairs [bp][k], 8192
  float2* szp = (float2*)(hs + 8192);        // z gate [jl][bp], 64
  float2* red = szp + 64;                    // [warp][16]
  const int tid = threadIdx.x, c = blockIdx.x;
  const int w = tid >> 5, lane = tid & 31;
  const int gate = w & 1, cpair = w >> 1;

  // load this CTA's weight slices into SMEM (one-time)
  for (int i = tid; i < 8192; i += 256){
    int jl = i & 7, k = i >> 3;
    int col = c*8 + jl;
    Ws[          jl*1024 + k] = Whz[(size_t)k*SS + col];
    Ws[ 8192  +  jl*1024 + k] = Whr[(size_t)k*SS + col];
    Ws[16384  +  jl*1024 + k] = Whn[(size_t)k*SS + col];
  }

  const float* Wa = Ws + gate*8192 + (cpair*2)*1024;
  const float* Wb = Wa + 1024;
  const float* Wn2 = Ws + 16384 + w*1024;
  const float* Gg = gate ? Gr : Gz;
  const ull* hglob  = (const ull*)g_hf;
  const ull* rhglob = (const ull*)g_rhf;

  for (int t = 0; t < TT; t++){
    // stage h (f32 pairs) -> smem, 128-bit copies
    for (int i = tid; i < 4096; i += 256)
      ((ulonglong2*)hs)[i] = ((const ulonglong2*)hglob)[i];
    __syncthreads();

    // ---- phase 1: z and r for 2 cols per warp ----
    {
      ull a0[8], a1[8];
      #pragma unroll
      for (int bp = 0; bp < 8; bp++){ a0[bp] = 0ull; a1[bp] = 0ull; }
      #pragma unroll 4
      for (int i = 0; i < 32; i++){
        int k = i*32 + lane;
        float wa = Wa[k], wb = Wb[k];
        ull W0 = pk2(wa, wa), W1 = pk2(wb, wb);
        #pragma unroll
        for (int bp = 0; bp < 8; bp++){
          ull h2 = hs[bp*1024 + k];
          ffma2(a0[bp], h2, W0);
          ffma2(a1[bp], h2, W1);
        }
      }
      #pragma unroll
      for (int bp = 0; bp < 8; bp++){ a0[bp] = redd(a0[bp]); a1[bp] = redd(a1[bp]); }
      if (lane == 0){
        #pragma unroll
        for (int bp = 0; bp < 8; bp++){
          red[w*16 + bp]     = *(float2*)&a0[bp];
          red[w*16 + 8 + bp] = *(float2*)&a1[bp];
        }
      }
      __syncwarp();
      if (lane < 16){
        int q = lane >> 3, bp = lane & 7;
        float2 v = red[w*16 + q*8 + bp];
        int j  = c*8 + cpair*2 + q;
        int m0 = t*16 + bp*2;
        float gv0 = Gg[(size_t)m0*SS + j];
        float gv1 = Gg[(size_t)(m0+1)*SS + j];
        float s0 = sigf(v.x + gv0), s1 = sigf(v.y + gv1);
        if (gate == 0){
          szp[(cpair*2 + q)*8 + bp] = make_float2(s0, s1);
        } else {
          float2 h2; *(ull*)&h2 = hs[bp*1024 + j];
          g_rhf[bp*1024 + j] = make_float2(s0*h2.x, s1*h2.y);
        }
      }
    }
    gsync();

    // stage r*h -> smem
    for (int i = tid; i < 4096; i += 256)
      ((ulonglong2*)hs)[i] = ((const ulonglong2*)rhglob)[i];
    __syncthreads();

    // ---- phase 2: n and h update (warp w -> col c*8+w) ----
    {
      ull acc[8];
      #pragma unroll
      for (int bp = 0; bp < 8; bp++) acc[bp] = 0ull;
      #pragma unroll 4
      for (int i = 0; i < 32; i++){
        int k = i*32 + lane;
        float wn = Wn2[k];
        ull Wv = pk2(wn, wn);
        #pragma unroll
        for (int bp = 0; bp < 8; bp++){
          ull h2 = hs[bp*1024 + k];
          ffma2(acc[bp], h2, Wv);
        }
      }
      #pragma unroll
      for (int bp = 0; bp < 8; bp++) acc[bp] = redd(acc[bp]);
      if (lane == 0){
        #pragma unroll
        for (int bp = 0; bp < 8; bp++) red[w*16 + bp] = *(float2*)&acc[bp];
      }
      __syncwarp();
      if (lane < 8){
        int bp = lane;
        float2 v = red[w*16 + bp];
        int j  = c*8 + w;
        int m0 = t*16 + bp*2;
        float n0 = tanhf(v.x + Gn[(size_t)m0*SS + j]);
        float n1 = tanhf(v.y + Gn[(size_t)(m0+1)*SS + j]);
        float2 z2 = szp[w*8 + bp];
        float2 ho = g_hf[bp*1024 + j];
        float h0 = ho.x + z2.x*(n0 - ho.x);
        float h1 = ho.y + z2.y*(n1 - ho.y);
        g_hf[bp*1024 + j] = make_float2(h0, h1);
        Hout[(size_t)m0*SS + j]     = h0;
        Hout[(size_t)(m0+1)*SS + j] = h1;
      }
    }
    gsync();
  }
}

// ---------------- h_final: out tail [l][b][s] (runs BEFORE output GEMM) -----
__global__ void hfin_k(const float* __restrict__ H1, float* __restrict__ out){
  int i = blockIdx.x*256 + threadIdx.x;   // 0..32767
  int l = i >> 14, rest = i & 16383;
  const float* H = l ? g_H2 : H1;
  out[i] = H[(size_t)(255*16 + (rest >> 10))*SS + (rest & 1023)];
}

// ---------------- launch -----------------------------------------------------
extern "C" void kernel_launch(void* const* d_in, const int* in_sizes, int n_in,
                              void* d_out, int out_size) {
  const int*   x   = (const int*)d_in[0];
  const float* emb = (const float*)d_in[1];
  const float* Wz  = (const float*)d_in[2];
  const float* bz  = (const float*)d_in[3];
  const float* Wr  = (const float*)d_in[4];
  const float* br  = (const float*)d_in[5];
  const float* Wn  = (const float*)d_in[6];
  const float* bn  = (const float*)d_in[7];
  const float* Wo  = (const float*)d_in[8];
  const float* bo  = (const float*)d_in[9];
  float* out = (float*)d_out;

  cudaFuncSetAttribute(gru_layer_k, cudaFuncAttributeMaxDynamicSharedMemorySize, GRU_DSMEM);

  void* pH2v; cudaGetSymbolAddress(&pH2v, g_H2);
  float* H2 = (float*)pH2v;

  // fp32 scratch inside d_out (dead before the output GEMM writes logits):
  float* Gz_s = out;                       // 16 MB
  float* Gr_s = out + (size_t)(4u<<20);    // 16 MB
  float* Gn_s = out + (size_t)(8u<<20);    // 16 MB
  float* H1   = out + (size_t)(12u<<20);   // 16 MB

  const size_t slab = (size_t)2048 * SS;   // per-layer W* slab ((E+S) x S)
  const size_t MSZ  = (size_t)SS * SS;     // h-part offset within slab

  embed_k<<<MM, 256>>>(x, emb, H2);        // X lives in g_H2 until layer 1

  for (int l = 0; l < 2; l++){
    const float* Al = (l == 0) ? (const float*)H2 : (const float*)H1;
    gemm_k<<<dim3(32,16), 256>>>(Al, Wz + l*slab, bz + l*SS, Gz_s, SS, SS, 0);
    gemm_k<<<dim3(32,16), 256>>>(Al, Wr + l*slab, br + l*SS, Gr_s, SS, SS, 0);
    gemm_k<<<dim3(32,16), 256>>>(Al, Wn + l*slab, bn + l*SS, Gn_s, SS, SS, 0);
    zero_h_k<<<32, 256>>>();
    float* Hout = l ? H2 : H1;
    gru_layer_k<<<RCTAS, 256, GRU_DSMEM>>>(
        Gz_s, Gr_s, Gn_s,
        Wz + l*slab + MSZ, Wr + l*slab + MSZ, Wn + l*slab + MSZ, Hout);
  }

  // h_final first (reads H1 scratch before logits overwrite it)
  hfin_k<<<RCTAS, 256>>>(H1, out + (size_t)MM*VV);

  // output projection: [4096,1024]@[1024,32000] + bo, rows remapped to [B,T]
  gemm_k<<<dim3(32,500), 256>>>(H2, Wo, bo, out, SS, VV, 1);
}

// round 12
// speedup vs baseline: 1.3805x; 1.3805x over previous
#include <cuda_runtime.h>
#include <cuda_bf16.h>
#include <cstdint>

#define TT 256
#define BB 16
#define SS 1024
#define VV 32000
#define MM 4096
#define RCTAS 128

typedef unsigned long long ull;

// ---------------- device statics (~32.4 MB) ---------------------------------
__device__ float         g_H2 [(size_t)MM*SS]; // layer-1 hidden (also X early)
__device__ __nv_bfloat16 g_Hhi[(size_t)MM*SS]; // bf16 hi split of current A
__device__ __nv_bfloat16 g_Hlo[(size_t)MM*SS]; // bf16 lo split
__device__ float2 g_hf [SS*8];                 // canonical h fp32 pairs [bp][k]
__device__ float2 g_rhf[SS*8];                 // r*h fp32 pairs [bp][k]
__device__ unsigned g_cnt, g_gen;

// ---------------- helpers ----------------------------------------------------
__device__ __forceinline__ ull pk2(float lo, float hi){
  ull r; asm("mov.b64 %0,{%1,%2};" : "=l"(r) : "f"(lo), "f"(hi)); return r;
}
__device__ __forceinline__ void ffma2(ull& c, ull a, ull b){
  asm("fma.rn.f32x2 %0,%1,%2,%0;" : "+l"(c) : "l"(a), "l"(b));
}
__device__ __forceinline__ ull redd(ull v){
  #pragma unroll
  for (int off = 16; off; off >>= 1){
    ull o = __shfl_xor_sync(0xffffffffu, v, off);
    asm("add.rn.f32x2 %0,%0,%1;" : "+l"(v) : "l"(o));
  }
  return v;
}
__device__ __forceinline__ unsigned packbf(float lo, float hi){
  unsigned r;
  asm("cvt.rn.bf16x2.f32 %0,%1,%2;" : "=r"(r) : "f"(hi), "f"(lo));
  return r;
}
__device__ __forceinline__ float sigf(float x){ return 1.f/(1.f+__expf(-x)); }

__device__ __forceinline__ uint32_t smem_u32(const void* p){
  uint32_t a;
  asm("{ .reg .u64 t; cvta.to.shared.u64 t, %1; cvt.u32.u64 %0, t; }" : "=r"(a) : "l"(p));
  return a;
}

// mma.sync m16n8k16 bf16 -> f32 (baseline PTX, runs on HMMA)
__device__ __forceinline__ void mma16816(float* c, const unsigned* a, const unsigned* b){
  asm volatile(
    "mma.sync.aligned.m16n8k16.row.col.f32.bf16.bf16.f32 "
    "{%0,%1,%2,%3}, {%4,%5,%6,%7}, {%8,%9}, {%0,%1,%2,%3};"
    : "+f"(c[0]), "+f"(c[1]), "+f"(c[2]), "+f"(c[3])
    : "r"(a[0]), "r"(a[1]), "r"(a[2]), "r"(a[3]), "r"(b[0]), "r"(b[1]));
}
__device__ __forceinline__ void ldsm4(unsigned* r, uint32_t addr){
  asm volatile("ldmatrix.sync.aligned.m8n8.x4.shared.b16 {%0,%1,%2,%3},[%4];"
    : "=r"(r[0]), "=r"(r[1]), "=r"(r[2]), "=r"(r[3]) : "r"(addr));
}
__device__ __forceinline__ void ldsm2t(unsigned* r, uint32_t addr){
  asm volatile("ldmatrix.sync.aligned.m8n8.x2.trans.shared.b16 {%0,%1},[%2];"
    : "=r"(r[0]), "=r"(r[1]) : "r"(addr));
}

// ---------------- grid barrier (release/acquire, 128 co-resident CTAs) ------
__device__ __forceinline__ void gsync(){
  __syncthreads();
  if (threadIdx.x == 0){
    unsigned g0, old;
    asm volatile("ld.acquire.gpu.u32 %0,[%1];" : "=r"(g0) : "l"(&g_gen));
    asm volatile("atom.add.release.gpu.u32 %0,[%1],%2;" : "=r"(old) : "l"(&g_cnt), "r"(1u));
    if (old == RCTAS - 1u){
      asm volatile("st.relaxed.gpu.u32 [%0],%1;" :: "l"(&g_cnt), "r"(0u));
      unsigned g1 = g0 + 1u;
      asm volatile("st.release.gpu.u32 [%0],%1;" :: "l"(&g_gen), "r"(g1));
    } else {
      unsigned cur;
      do {
        __nanosleep(32);
        asm volatile("ld.acquire.gpu.u32 %0,[%1];" : "=r"(cur) : "l"(&g_gen));
      } while (cur == g0);
    }
  }
  __syncthreads();
}

// ---------------- embedding gather ------------------------------------------
__global__ void embed_k(const int* __restrict__ x, const float* __restrict__ emb,
                        float* __restrict__ X){
  int m = blockIdx.x;
  int t = m >> 4, b = m & 15;
  int tok = x[b*TT + t];
  float4 v = *(const float4*)(emb + (size_t)tok*SS + threadIdx.x*4);
  *(float4*)(X + (size_t)m*SS + threadIdx.x*4) = v;
}

__global__ void zero_h_k(){
  int i = blockIdx.x*256 + threadIdx.x;
  g_hf[i] = make_float2(0.f, 0.f);
}

// ---------------- split fp32 -> bf16 hi/lo (A operand prep) -----------------
__global__ void split_k(const float* __restrict__ H){
  size_t i = ((size_t)blockIdx.x*256 + threadIdx.x)*4;
  float4 v = *(const float4*)(H + i);
  float f[4] = {v.x, v.y, v.z, v.w};
  unsigned short hs[4]; float lo[4];
  #pragma unroll
  for (int j = 0; j < 4; j++){
    __nv_bfloat16 b = __float2bfloat16(f[j]);
    hs[j] = *(unsigned short*)&b;
    lo[j] = f[j] - __bfloat162float(b);
  }
  uint2 hp, lp;
  hp.x = ((unsigned)hs[1] << 16) | hs[0];
  hp.y = ((unsigned)hs[3] << 16) | hs[2];
  lp.x = packbf(lo[0], lo[1]);
  lp.y = packbf(lo[2], lo[3]);
  *(uint2*)(g_Hhi + i) = hp;
  *(uint2*)(g_Hlo + i) = lp;
}

// ---------------- mma.sync bf16-split GEMM -----------------------------------
// C[4096, N] = (Ahi+Alo)[4096,1024] @ B[1024,N] + bias (B fp32, split on the fly)
// Tile 128x128x32, 256 thr, warp tile 64x32, 3 MMAs per frag pair (hi*hi,hi*lo,lo*hi).
#define SKA 40
#define SKB 136
__global__ __launch_bounds__(256, 1) void mgemm_k(
    const __nv_bfloat16* __restrict__ Ahi, const __nv_bfloat16* __restrict__ Alo,
    const float* __restrict__ B, const float* __restrict__ bias,
    float* __restrict__ C, int N, int remap)
{
  __shared__ __nv_bfloat16 sAh[128*SKA], sAl[128*SKA];
  __shared__ __nv_bfloat16 sBh[32*SKB],  sBl[32*SKB];
  const int tid = threadIdx.x, lane = tid & 31, w = tid >> 5;
  const int wm = w & 1, wn = w >> 1;            // 2 m-warps x 4 n-warps
  const int mbase = blockIdx.x*128, n0 = blockIdx.y*128;

  float acc[4][4][4];
  #pragma unroll
  for (int a = 0; a < 4; a++)
    #pragma unroll
    for (int b = 0; b < 4; b++)
      #pragma unroll
      for (int c = 0; c < 4; c++) acc[a][b][c] = 0.f;

  // per-thread load coords
  const int arow = tid >> 1, aq = (tid & 1)*16;          // A: row, 16 k elems
  const int bkr = tid >> 5, bnq = (tid & 31)*4;          // B: k row (+8*s), 4 n
  const uint32_t sAh0 = smem_u32(sAh), sAl0 = smem_u32(sAl);
  const uint32_t sBh0 = smem_u32(sBh), sBl0 = smem_u32(sBl);

  uint4 rah0, rah1, ral0, ral1;
  float4 rb[4];

  // prologue loads (kc = 0)
  {
    const __nv_bfloat16* pa = Ahi + (size_t)(mbase + arow)*SS + aq;
    const __nv_bfloat16* pl = Alo + (size_t)(mbase + arow)*SS + aq;
    rah0 = *(const uint4*)pa; rah1 = *(const uint4*)(pa + 8);
    ral0 = *(const uint4*)pl; ral1 = *(const uint4*)(pl + 8);
    #pragma unroll
    for (int s = 0; s < 4; s++)
      rb[s] = *(const float4*)(B + (size_t)(bkr + s*8)*N + n0 + bnq);
  }

  for (int kc = 0; kc < 32; kc++){
    // store staged tile to smem
    *(uint4*)&sAh[arow*SKA + aq] = rah0;  *(uint4*)&sAh[arow*SKA + aq + 8] = rah1;
    *(uint4*)&sAl[arow*SKA + aq] = ral0;  *(uint4*)&sAl[arow*SKA + aq + 8] = ral1;
    #pragma unroll
    for (int s = 0; s < 4; s++){
      float4 v = rb[s];
      unsigned hp0 = packbf(v.x, v.y), hp1 = packbf(v.z, v.w);
      float hx = __uint_as_float(hp0 << 16), hy = __uint_as_float(hp0 & 0xffff0000u);
      float hz = __uint_as_float(hp1 << 16), hw = __uint_as_float(hp1 & 0xffff0000u);
      unsigned lp0 = packbf(v.x - hx, v.y - hy), lp1 = packbf(v.z - hz, v.w - hw);
      int off = (bkr + s*8)*SKB + bnq;
      *(uint2*)&sBh[off] = make_uint2(hp0, hp1);
      *(uint2*)&sBl[off] = make_uint2(lp0, lp1);
    }
    __syncthreads();

    // prefetch next tile
    if (kc < 31){
      int k0 = (kc + 1)*32;
      const __nv_bfloat16* pa = Ahi + (size_t)(mbase + arow)*SS + k0 + aq;
      const __nv_bfloat16* pl = Alo + (size_t)(mbase + arow)*SS + k0 + aq;
      rah0 = *(const uint4*)pa; rah1 = *(const uint4*)(pa + 8);
      ral0 = *(const uint4*)pl; ral1 = *(const uint4*)(pl + 8);
      #pragma unroll
      for (int s = 0; s < 4; s++)
        rb[s] = *(const float4*)(B + (size_t)(k0 + bkr + s*8)*N + n0 + bnq);
    }

    // compute: 2 k-steps of 16
    #pragma unroll
    for (int ks = 0; ks < 2; ks++){
      const int k0 = ks*16;
      unsigned af[2][4][4];
      const int am = wm*64 + ((lane >> 3) & 1)*8 + (lane & 7);
      const int ak = k0 + (lane >> 4)*8;
      #pragma unroll
      for (int mf = 0; mf < 4; mf++){
        int off = ((am + mf*16)*SKA + ak)*2;
        ldsm4(af[0][mf], sAh0 + off);
        ldsm4(af[1][mf], sAl0 + off);
      }
      unsigned bfr[2][4][2];
      const int brow = k0 + (lane & 15);
      #pragma unroll
      for (int nf = 0; nf < 4; nf++){
        int off = (brow*SKB + wn*32 + nf*8)*2;
        ldsm2t(bfr[0][nf], sBh0 + off);
        ldsm2t(bfr[1][nf], sBl0 + off);
      }
      #pragma unroll
      for (int mf = 0; mf < 4; mf++)
        #pragma unroll
        for (int nf = 0; nf < 4; nf++){
          mma16816(acc[mf][nf], af[0][mf], bfr[0][nf]);
          mma16816(acc[mf][nf], af[0][mf], bfr[1][nf]);
          mma16816(acc[mf][nf], af[1][mf], bfr[0][nf]);
        }
    }
    __syncthreads();
  }

  // epilogue
  #pragma unroll
  for (int mf = 0; mf < 4; mf++){
    #pragma unroll
    for (int r2 = 0; r2 < 2; r2++){
      int mg = mbase + wm*64 + mf*16 + (lane >> 2) + r2*8;
      int row = remap ? ((mg & 15)*TT + (mg >> 4)) : mg;
      float* dst = C + (size_t)row*N + n0 + wn*32;
      #pragma unroll
      for (int nf = 0; nf < 4; nf++){
        int col = nf*8 + (lane & 3)*2;
        float b0 = bias[n0 + wn*32 + col];
        float b1 = bias[n0 + wn*32 + col + 1];
        float2 v = make_float2(acc[mf][nf][r2*2] + b0, acc[mf][nf][r2*2 + 1] + b1);
        *(float2*)(dst + col) = v;
      }
    }
  }
}

// ---------------- persistent GRU layer recurrence (fp32, unchanged) ---------
#define GRU_DSMEM (98304 + 65536 + 512 + 1024)
__global__ __launch_bounds__(256, 1) void gru_layer_k(
    const float* __restrict__ Gz, const float* __restrict__ Gr,
    const float* __restrict__ Gn,
    const float* __restrict__ Whz, const float* __restrict__ Whr,
    const float* __restrict__ Whn, float* __restrict__ Hout)
{
  extern __shared__ __align__(16) float dynf[];
  float*  Ws  = dynf;                        // 3*8*1024 f32 [g][jl][k]
  ull*    hs  = (ull*)(dynf + 24576);        // f32x2 pairs [bp][k], 8192
  float2* szp = (float2*)(hs + 8192);        // z gate [jl][bp], 64
  float2* red = szp + 64;                    // [warp][16]
  const int tid = threadIdx.x, c = blockIdx.x;
  const int w = tid >> 5, lane = tid & 31;
  const int gate = w & 1, cpair = w >> 1;

  for (int i = tid; i < 8192; i += 256){
    int jl = i & 7, k = i >> 3;
    int col = c*8 + jl;
    Ws[          jl*1024 + k] = Whz[(size_t)k*SS + col];
    Ws[ 8192  +  jl*1024 + k] = Whr[(size_t)k*SS + col];
    Ws[16384  +  jl*1024 + k] = Whn[(size_t)k*SS + col];
  }

  const float* Wa = Ws + gate*8192 + (cpair*2)*1024;
  const float* Wb = Wa + 1024;
  const float* Wn2 = Ws + 16384 + w*1024;
  const float* Gg = gate ? Gr : Gz;
  const ull* hglob  = (const ull*)g_hf;
  const ull* rhglob = (const ull*)g_rhf;

  for (int t = 0; t < TT; t++){
    for (int i = tid; i < 4096; i += 256)
      ((ulonglong2*)hs)[i] = ((const ulonglong2*)hglob)[i];
    __syncthreads();

    { // phase 1: z and r
      ull a0[8], a1[8];
      #pragma unroll
      for (int bp = 0; bp < 8; bp++){ a0[bp] = 0ull; a1[bp] = 0ull; }
      #pragma unroll 4
      for (int i = 0; i < 32; i++){
        int k = i*32 + lane;
        float wa = Wa[k], wb = Wb[k];
        ull W0 = pk2(wa, wa), W1 = pk2(wb, wb);
        #pragma unroll
        for (int bp = 0; bp < 8; bp++){
          ull h2 = hs[bp*1024 + k];
          ffma2(a0[bp], h2, W0);
          ffma2(a1[bp], h2, W1);
        }
      }
      #pragma unroll
      for (int bp = 0; bp < 8; bp++){ a0[bp] = redd(a0[bp]); a1[bp] = redd(a1[bp]); }
      if (lane == 0){
        #pragma unroll
        for (int bp = 0; bp < 8; bp++){
          red[w*16 + bp]     = *(float2*)&a0[bp];
          red[w*16 + 8 + bp] = *(float2*)&a1[bp];
        }
      }
      __syncwarp();
      if (lane < 16){
        int q = lane >> 3, bp = lane & 7;
        float2 v = red[w*16 + q*8 + bp];
        int j  = c*8 + cpair*2 + q;
        int m0 = t*16 + bp*2;
        float gv0 = Gg[(size_t)m0*SS + j];
        float gv1 = Gg[(size_t)(m0+1)*SS + j];
        float s0 = sigf(v.x + gv0), s1 = sigf(v.y + gv1);
        if (gate == 0){
          szp[(cpair*2 + q)*8 + bp] = make_float2(s0, s1);
        } else {
          float2 h2; *(ull*)&h2 = hs[bp*1024 + j];
          g_rhf[bp*1024 + j] = make_float2(s0*h2.x, s1*h2.y);
        }
      }
    }
    gsync();

    for (int i = tid; i < 4096; i += 256)
      ((ulonglong2*)hs)[i] = ((const ulonglong2*)rhglob)[i];
    __syncthreads();

    { // phase 2: n and h update
      ull acc[8];
      #pragma unroll
      for (int bp = 0; bp < 8; bp++) acc[bp] = 0ull;
      #pragma unroll 4
      for (int i = 0; i < 32; i++){
        int k = i*32 + lane;
        float wn = Wn2[k];
        ull Wv = pk2(wn, wn);
        #pragma unroll
        for (int bp = 0; bp < 8; bp++){
          ull h2 = hs[bp*1024 + k];
          ffma2(acc[bp], h2, Wv);
        }
      }
      #pragma unroll
      for (int bp = 0; bp < 8; bp++) acc[bp] = redd(acc[bp]);
      if (lane == 0){
        #pragma unroll
        for (int bp = 0; bp < 8; bp++) red[w*16 + bp] = *(float2*)&acc[bp];
      }
      __syncwarp();
      if (lane < 8){
        int bp = lane;
        float2 v = red[w*16 + bp];
        int j  = c*8 + w;
        int m0 = t*16 + bp*2;
        float n0 = tanhf(v.x + Gn[(size_t)m0*SS + j]);
        float n1 = tanhf(v.y + Gn[(size_t)(m0+1)*SS + j]);
        float2 z2 = szp[w*8 + bp];
        float2 ho = g_hf[bp*1024 + j];
        float h0 = ho.x + z2.x*(n0 - ho.x);
        float h1 = ho.y + z2.y*(n1 - ho.y);
        g_hf[bp*1024 + j] = make_float2(h0, h1);
        Hout[(size_t)m0*SS + j]     = h0;
        Hout[(size_t)(m0+1)*SS + j] = h1;
      }
    }
    gsync();
  }
}

// ---------------- h_final tail ----------------------------------------------
__global__ void hfin_k(const float* __restrict__ H1, float* __restrict__ out){
  int i = blockIdx.x*256 + threadIdx.x;   // 0..32767
  int l = i >> 14, rest = i & 16383;
  const float* H = l ? g_H2 : H1;
  out[i] = H[(size_t)(255*16 + (rest >> 10))*SS + (rest & 1023)];
}

// ---------------- launch -----------------------------------------------------
extern "C" void kernel_launch(void* const* d_in, const int* in_sizes, int n_in,
                              void* d_out, int out_size) {
  const int*   x   = (const int*)d_in[0];
  const float* emb = (const float*)d_in[1];
  const float* Wz  = (const float*)d_in[2];
  const float* bz  = (const float*)d_in[3];
  const float* Wr  = (const float*)d_in[4];
  const float* br  = (const float*)d_in[5];
  const float* Wn  = (const float*)d_in[6];
  const float* bn  = (const float*)d_in[7];
  const float* Wo  = (const float*)d_in[8];
  const float* bo  = (const float*)d_in[9];
  float* out = (float*)d_out;

  cudaFuncSetAttribute(gru_layer_k, cudaFuncAttributeMaxDynamicSharedMemorySize, GRU_DSMEM);

  void* pH2v; cudaGetSymbolAddress(&pH2v, g_H2);
  float* H2 = (float*)pH2v;
  void* pHhi; cudaGetSymbolAddress(&pHhi, g_Hhi);
  void* pHlo; cudaGetSymbolAddress(&pHlo, g_Hlo);
  const __nv_bfloat16* Hhi = (const __nv_bfloat16*)pHhi;
  const __nv_bfloat16* Hlo = (const __nv_bfloat16*)pHlo;

  // fp32 scratch inside d_out (dead before the output GEMM writes logits):
  float* Gz_s = out;                       // 16 MB
  float* Gr_s = out + (size_t)(4u<<20);    // 16 MB
  float* Gn_s = out + (size_t)(8u<<20);    // 16 MB
  float* H1   = out + (size_t)(12u<<20);   // 16 MB

  const size_t slab = (size_t)2048 * SS;   // per-layer W* slab ((E+S) x S)
  const size_t MSZ  = (size_t)SS * SS;     // h-part offset within slab

  embed_k<<<MM, 256>>>(x, emb, H2);        // X lives in g_H2 until layer 1
  split_k<<<4096, 256>>>(H2);              // A operand = X

  for (int l = 0; l < 2; l++){
    mgemm_k<<<dim3(32, 8), 256>>>(Hhi, Hlo, Wz + l*slab, bz + l*SS, Gz_s, SS, 0);
    mgemm_k<<<dim3(32, 8), 256>>>(Hhi, Hlo, Wr + l*slab, br + l*SS, Gr_s, SS, 0);
    mgemm_k<<<dim3(32, 8), 256>>>(Hhi, Hlo, Wn + l*slab, bn + l*SS, Gn_s, SS, 0);
    zero_h_k<<<32, 256>>>();
    float* Hout = l ? H2 : H1;
    gru_layer_k<<<RCTAS, 256, GRU_DSMEM>>>(
        Gz_s, Gr_s, Gn_s,
        Wz + l*slab + MSZ, Wr + l*slab + MSZ, Wn + l*slab + MSZ, Hout);
    split_k<<<4096, 256>>>(Hout);          // A operand for next stage
  }

  // h_final first (reads H1 scratch before logits overwrite it)
  hfin_k<<<RCTAS, 256>>>(H1, out + (size_t)MM*VV);

  // output projection: [4096,1024]@[1024,32000] + bo, rows remapped to [B,T]
  mgemm_k<<<dim3(32, 250), 256>>>(Hhi, Hlo, Wo, bo, out, VV, 1);
}

// round 16
// speedup vs baseline: 1.4037x; 1.0169x over previous
#include <cuda_runtime.h>
#include <cuda_bf16.h>
#include <cstdint>

#define TT 256
#define BB 16
#define SS 1024
#define VV 32000
#define MM 4096
#define RCTAS 128

typedef unsigned long long ull;

// ---------------- device statics (~32.4 MB) ---------------------------------
__device__ float         g_H2 [(size_t)MM*SS]; // layer-1 hidden (also X early)
__device__ __nv_bfloat16 g_Hhi[(size_t)MM*SS]; // bf16 hi split of current A
__device__ __nv_bfloat16 g_Hlo[(size_t)MM*SS]; // bf16 lo split
__device__ float2 g_hf [SS*8];                 // canonical h fp32 pairs [bp][k]
__device__ float2 g_rhf[SS*8];                 // r*h fp32 pairs [bp][k]
__device__ unsigned g_cnt, g_gen;

// ---------------- helpers ----------------------------------------------------
__device__ __forceinline__ ull pk2(float lo, float hi){
  ull r; asm("mov.b64 %0,{%1,%2};" : "=l"(r) : "f"(lo), "f"(hi)); return r;
}
__device__ __forceinline__ void ffma2(ull& c, ull a, ull b){
  asm("fma.rn.f32x2 %0,%1,%2,%0;" : "+l"(c) : "l"(a), "l"(b));
}
__device__ __forceinline__ ull redd(ull v){
  #pragma unroll
  for (int off = 16; off; off >>= 1){
    ull o = __shfl_xor_sync(0xffffffffu, v, off);
    asm("add.rn.f32x2 %0,%0,%1;" : "+l"(v) : "l"(o));
  }
  return v;
}
__device__ __forceinline__ unsigned packbf(float lo, float hi){
  unsigned r;
  asm("cvt.rn.bf16x2.f32 %0,%1,%2;" : "=r"(r) : "f"(hi), "f"(lo));
  return r;
}
__device__ __forceinline__ float sigf(float x){ return 1.f/(1.f+__expf(-x)); }

__device__ __forceinline__ uint32_t smem_u32(const void* p){
  uint32_t a;
  asm("{ .reg .u64 t; cvta.to.shared.u64 t, %1; cvt.u32.u64 %0, t; }" : "=r"(a) : "l"(p));
  return a;
}

// mma.sync m16n8k16 bf16 -> f32 (baseline PTX, runs on HMMA)
__device__ __forceinline__ void mma16816(float* c, const unsigned* a, const unsigned* b){
  asm volatile(
    "mma.sync.aligned.m16n8k16.row.col.f32.bf16.bf16.f32 "
    "{%0,%1,%2,%3}, {%4,%5,%6,%7}, {%8,%9}, {%0,%1,%2,%3};"
    : "+f"(c[0]), "+f"(c[1]), "+f"(c[2]), "+f"(c[3])
    : "r"(a[0]), "r"(a[1]), "r"(a[2]), "r"(a[3]), "r"(b[0]), "r"(b[1]));
}
__device__ __forceinline__ void ldsm4(unsigned* r, uint32_t addr){
  asm volatile("ldmatrix.sync.aligned.m8n8.x4.shared.b16 {%0,%1,%2,%3},[%4];"
    : "=r"(r[0]), "=r"(r[1]), "=r"(r[2]), "=r"(r[3]) : "r"(addr));
}
__device__ __forceinline__ void ldsm2t(unsigned* r, uint32_t addr){
  asm volatile("ldmatrix.sync.aligned.m8n8.x2.trans.shared.b16 {%0,%1},[%2];"
    : "=r"(r[0]), "=r"(r[1]) : "r"(addr));
}

// ---------------- grid barrier (release/acquire, 128 co-resident CTAs) ------
__device__ __forceinline__ void gsync(){
  __syncthreads();
  if (threadIdx.x == 0){
    unsigned g0, old;
    asm volatile("ld.acquire.gpu.u32 %0,[%1];" : "=r"(g0) : "l"(&g_gen));
    asm volatile("atom.add.release.gpu.u32 %0,[%1],%2;" : "=r"(old) : "l"(&g_cnt), "r"(1u));
    if (old == RCTAS - 1u){
      asm volatile("st.relaxed.gpu.u32 [%0],%1;" :: "l"(&g_cnt), "r"(0u));
      unsigned g1 = g0 + 1u;
      asm volatile("st.release.gpu.u32 [%0],%1;" :: "l"(&g_gen), "r"(g1));
    } else {
      unsigned cur;
      do {
        __nanosleep(32);
        asm volatile("ld.acquire.gpu.u32 %0,[%1];" : "=r"(cur) : "l"(&g_gen));
      } while (cur == g0);
    }
  }
  __syncthreads();
}

// ---------------- embedding gather ------------------------------------------
__global__ void embed_k(const int* __restrict__ x, const float* __restrict__ emb,
                        float* __restrict__ X){
  int m = blockIdx.x;
  int t = m >> 4, b = m & 15;
  int tok = x[b*TT + t];
  float4 v = *(const float4*)(emb + (size_t)tok*SS + threadIdx.x*4);
  *(float4*)(X + (size_t)m*SS + threadIdx.x*4) = v;
}

__global__ void zero_h_k(){
  int i = blockIdx.x*256 + threadIdx.x;
  g_hf[i] = make_float2(0.f, 0.f);
}

// ---------------- split fp32 -> bf16 hi/lo (A operand prep) -----------------
__global__ void split_k(const float* __restrict__ H){
  size_t i = ((size_t)blockIdx.x*256 + threadIdx.x)*4;
  float4 v = *(const float4*)(H + i);
  float f[4] = {v.x, v.y, v.z, v.w};
  unsigned short hs4[4]; float lo[4];
  #pragma unroll
  for (int j = 0; j < 4; j++){
    __nv_bfloat16 b = __float2bfloat16(f[j]);
    hs4[j] = *(unsigned short*)&b;
    lo[j] = f[j] - __bfloat162float(b);
  }
  uint2 hp, lp;
  hp.x = ((unsigned)hs4[1] << 16) | hs4[0];
  hp.y = ((unsigned)hs4[3] << 16) | hs4[2];
  lp.x = packbf(lo[0], lo[1]);
  lp.y = packbf(lo[2], lo[3]);
  *(uint2*)(g_Hhi + i) = hp;
  *(uint2*)(g_Hlo + i) = lp;
}

// ---------------- mma.sync bf16-split GEMM, double-buffered smem -------------
// C[4096, N] = (Ahi+Alo)[4096,1024] @ B[1024,N] + bias (B fp32, split on the fly)
// Tile 128x128x32, 256 thr, warp tile 64x32, 3 MMAs per frag pair.
#define SKA 40
#define SKB 136
#define OFF_AH 0
#define OFF_AL 10240
#define OFF_BH 20480
#define OFF_BL 29184
#define BUFSZ  37888
#define MG_SMEM (2*BUFSZ)
__global__ __launch_bounds__(256, 1) void mgemm_k(
    const __nv_bfloat16* __restrict__ Ahi, const __nv_bfloat16* __restrict__ Alo,
    const float* __restrict__ B, const float* __restrict__ bias,
    float* __restrict__ C, int N, int remap)
{
  extern __shared__ __align__(16) char msm[];
  const uint32_t s0 = smem_u32(msm);
  const int tid = threadIdx.x, lane = tid & 31, w = tid >> 5;
  const int wm = w & 1, wn = w >> 1;            // 2 m-warps x 4 n-warps
  const int mbase = blockIdx.x*128, n0 = blockIdx.y*128;

  float acc[4][4][4];
  #pragma unroll
  for (int a = 0; a < 4; a++)
    #pragma unroll
    for (int b = 0; b < 4; b++)
      #pragma unroll
      for (int c = 0; c < 4; c++) acc[a][b][c] = 0.f;

  const int arow = tid >> 1, aq = (tid & 1)*16;          // A: row, 16 k elems
  const int bkr = tid >> 5, bnq = (tid & 31)*4;          // B: k row (+8*s), 4 n

  uint4 rah0, rah1, ral0, ral1;
  float4 rb[4];

  // store staged regs into buffer `buf`
  auto store_tile = [&](int buf){
    char* bc = msm + buf*BUFSZ;
    *(uint4*)(bc + OFF_AH + (arow*SKA + aq)*2)     = rah0;
    *(uint4*)(bc + OFF_AH + (arow*SKA + aq + 8)*2) = rah1;
    *(uint4*)(bc + OFF_AL + (arow*SKA + aq)*2)     = ral0;
    *(uint4*)(bc + OFF_AL + (arow*SKA + aq + 8)*2) = ral1;
    #pragma unroll
    for (int s = 0; s < 4; s++){
      float4 v = rb[s];
      unsigned hp0 = packbf(v.x, v.y), hp1 = packbf(v.z, v.w);
      float hx = __uint_as_float(hp0 << 16), hy = __uint_as_float(hp0 & 0xffff0000u);
      float hz = __uint_as_float(hp1 << 16), hw = __uint_as_float(hp1 & 0xffff0000u);
      unsigned lp0 = packbf(v.x - hx, v.y - hy), lp1 = packbf(v.z - hz, v.w - hw);
      int off = ((bkr + s*8)*SKB + bnq)*2;
      *(uint2*)(bc + OFF_BH + off) = make_uint2(hp0, hp1);
      *(uint2*)(bc + OFF_BL + off) = make_uint2(lp0, lp1);
    }
  };
  auto load_tile = [&](int k0){
    const __nv_bfloat16* pa = Ahi + (size_t)(mbase + arow)*SS + k0 + aq;
    const __nv_bfloat16* pl = Alo + (size_t)(mbase + arow)*SS + k0 + aq;
    rah0 = *(const uint4*)pa; rah1 = *(const uint4*)(pa + 8);
    ral0 = *(const uint4*)pl; ral1 = *(const uint4*)(pl + 8);
    #pragma unroll
    for (int s = 0; s < 4; s++)
      rb[s] = *(const float4*)(B + (size_t)(k0 + bkr + s*8)*N + n0 + bnq);
  };

  load_tile(0);
  store_tile(0);
  __syncthreads();

  for (int kc = 0; kc < 32; kc++){
    const int cur = kc & 1;
    if (kc < 31) load_tile((kc + 1)*32);   // prefetch (latency hidden by MMAs)

    const uint32_t base = s0 + cur*BUFSZ;
    #pragma unroll
    for (int ks = 0; ks < 2; ks++){
      const int k0 = ks*16;
      unsigned af[2][4][4];
      const int am = wm*64 + ((lane >> 3) & 1)*8 + (lane & 7);
      const int ak = k0 + (lane >> 4)*8;
      #pragma unroll
      for (int mf = 0; mf < 4; mf++){
        int off = ((am + mf*16)*SKA + ak)*2;
        ldsm4(af[0][mf], base + OFF_AH + off);
        ldsm4(af[1][mf], base + OFF_AL + off);
      }
      unsigned bfr[2][4][2];
      const int brow = k0 + (lane & 15);
      #pragma unroll
      for (int nf = 0; nf < 4; nf++){
        int off = (brow*SKB + wn*32 + nf*8)*2;
        ldsm2t(bfr[0][nf], base + OFF_BH + off);
        ldsm2t(bfr[1][nf], base + OFF_BL + off);
      }
      #pragma unroll
      for (int mf = 0; mf < 4; mf++)
        #pragma unroll
        for (int nf = 0; nf < 4; nf++){
          mma16816(acc[mf][nf], af[0][mf], bfr[0][nf]);
          mma16816(acc[mf][nf], af[0][mf], bfr[1][nf]);
          mma16816(acc[mf][nf], af[1][mf], bfr[0][nf]);
        }
    }

    if (kc < 31) store_tile(cur ^ 1);
    __syncthreads();
  }

  // epilogue
  #pragma unroll
  for (int mf = 0; mf < 4; mf++){
    #pragma unroll
    for (int r2 = 0; r2 < 2; r2++){
      int mg = mbase + wm*64 + mf*16 + (lane >> 2) + r2*8;
      int row = remap ? ((mg & 15)*TT + (mg >> 4)) : mg;
      float* dst = C + (size_t)row*N + n0 + wn*32;
      #pragma unroll
      for (int nf = 0; nf < 4; nf++){
        int col = nf*8 + (lane & 3)*2;
        float b0 = bias[n0 + wn*32 + col];
        float b1 = bias[n0 + wn*32 + col + 1];
        float2 v = make_float2(acc[mf][nf][r2*2] + b0, acc[mf][nf][r2*2 + 1] + b1);
        *(float2*)(dst + col) = v;
      }
    }
  }
}

// ---------------- persistent GRU layer recurrence (fp32, LDS/FMA balanced) --
// 128 CTAs x 256 thr. CTA c owns state cols [c*8, c*8+8). W_h slices in SMEM.
// Phase1: warp role (gate=w&1, khalf=(w>>1)&1, bphalf=w>>2): 8 cols x 4 bp
//         over 512 k. Phase2: (kq=w&3, bphalf=w>>2): 8 cols x 4 bp over 256 k.
// Cross-warp partials combined in `red` by finisher threads.
#define GRU_DSMEM (98304 + 65536 + 512 + 2048)
__global__ __launch_bounds__(256, 1) void gru_layer_k(
    const float* __restrict__ Gz, const float* __restrict__ Gr,
    const float* __restrict__ Gn,
    const float* __restrict__ Whz, const float* __restrict__ Whr,
    const float* __restrict__ Whn, float* __restrict__ Hout)
{
  extern __shared__ __align__(16) float dynf[];
  float*  Ws  = dynf;                        // 3*8*1024 f32 [g][jl][k]
  ull*    hs  = (ull*)(dynf + 24576);        // f32x2 pairs [bp][k], 8192
  float2* szp = (float2*)(hs + 8192);        // z gate [jl][bp], 64
  float2* red = szp + 64;                    // [warp][32] partials
  const int tid = threadIdx.x, c = blockIdx.x;
  const int w = tid >> 5, lane = tid & 31;

  // load this CTA's weight slices into SMEM (one-time)
  for (int i = tid; i < 8192; i += 256){
    int jl = i & 7, k = i >> 3;
    int col = c*8 + jl;
    Ws[          jl*1024 + k] = Whz[(size_t)k*SS + col];
    Ws[ 8192  +  jl*1024 + k] = Whr[(size_t)k*SS + col];
    Ws[16384  +  jl*1024 + k] = Whn[(size_t)k*SS + col];
  }

  const ull* hglob  = (const ull*)g_hf;
  const ull* rhglob = (const ull*)g_rhf;

  for (int t = 0; t < TT; t++){
    // stage h (f32 pairs) -> smem
    for (int i = tid; i < 4096; i += 256)
      ((ulonglong2*)hs)[i] = ((const ulonglong2*)hglob)[i];
    __syncthreads();

    // ---- phase 1: z and r. warp = (gate, khalf, bphalf) ----
    {
      const int gate = w & 1, kh = (w >> 1) & 1, bh = w >> 2;
      const int kbase = kh*512;
      const float* Wg = Ws + gate*8192;
      const ull* hp = hs + (bh*4)*1024;
      ull acc[8][4];
      #pragma unroll
      for (int c8 = 0; c8 < 8; c8++)
        #pragma unroll
        for (int b = 0; b < 4; b++) acc[c8][b] = 0ull;
      #pragma unroll 2
      for (int i = 0; i < 16; i++){
        int k = kbase + i*32 + lane;
        ull h0 = hp[k], h1 = hp[k+1024], h2 = hp[k+2048], h3 = hp[k+3072];
        #pragma unroll
        for (int c8 = 0; c8 < 8; c8++){
          float wv = Wg[c8*1024 + k];
          ull W2 = pk2(wv, wv);
          ffma2(acc[c8][0], h0, W2);
          ffma2(acc[c8][1], h1, W2);
          ffma2(acc[c8][2], h2, W2);
          ffma2(acc[c8][3], h3, W2);
        }
      }
      #pragma unroll
      for (int c8 = 0; c8 < 8; c8++)
        #pragma unroll
        for (int b = 0; b < 4; b++) acc[c8][b] = redd(acc[c8][b]);
      if (lane == 0){
        #pragma unroll
        for (int c8 = 0; c8 < 8; c8++)
          #pragma unroll
          for (int b = 0; b < 4; b++)
            red[w*32 + c8*4 + b] = *(float2*)&acc[c8][b];
      }
      __syncthreads();
      if (tid < 128){
        int g  = tid & 1, bh2 = (tid >> 1) & 1, c8 = (tid >> 2) & 7, b = (tid >> 5) & 3;
        float2 v0 = red[(g + bh2*4)*32 + c8*4 + b];
        float2 v1 = red[(g + 2 + bh2*4)*32 + c8*4 + b];
        float vx = v0.x + v1.x, vy = v0.y + v1.y;
        int j = c*8 + c8, bp = bh2*4 + b, m0 = t*16 + bp*2;
        const float* Gg = g ? Gr : Gz;
        float s0 = sigf(vx + Gg[(size_t)m0*SS + j]);
        float s1 = sigf(vy + Gg[(size_t)(m0+1)*SS + j]);
        if (g == 0){
          szp[c8*8 + bp] = make_float2(s0, s1);
        } else {
          float2 h2v; *(ull*)&h2v = hs[bp*1024 + j];
          g_rhf[bp*1024 + j] = make_float2(s0*h2v.x, s1*h2v.y);
        }
      }
    }
    gsync();

    // stage r*h -> smem
    for (int i = tid; i < 4096; i += 256)
      ((ulonglong2*)hs)[i] = ((const ulonglong2*)rhglob)[i];
    __syncthreads();

    // ---- phase 2: n and h update. warp = (kq, bphalf) ----
    {
      const int kq = w & 3, bh = w >> 2;
      const int kbase = kq*256;
      const float* Wg = Ws + 16384;
      const ull* hp = hs + (bh*4)*1024;
      ull acc[8][4];
      #pragma unroll
      for (int c8 = 0; c8 < 8; c8++)
        #pragma unroll
        for (int b = 0; b < 4; b++) acc[c8][b] = 0ull;
      #pragma unroll 2
      for (int i = 0; i < 8; i++){
        int k = kbase + i*32 + lane;
        ull h0 = hp[k], h1 = hp[k+1024], h2 = hp[k+2048], h3 = hp[k+3072];
        #pragma unroll
        for (int c8 = 0; c8 < 8; c8++){
          float wv = Wg[c8*1024 + k];
          ull W2 = pk2(wv, wv);
          ffma2(acc[c8][0], h0, W2);
          ffma2(acc[c8][1], h1, W2);
          ffma2(acc[c8][2], h2, W2);
          ffma2(acc[c8][3], h3, W2);
        }
      }
      #pragma unroll
      for (int c8 = 0; c8 < 8; c8++)
        #pragma unroll
        for (int b = 0; b < 4; b++) acc[c8][b] = redd(acc[c8][b]);
      if (lane == 0){
        #pragma unroll
        for (int c8 = 0; c8 < 8; c8++)
          #pragma unroll
          for (int b = 0; b < 4; b++)
            red[w*32 + c8*4 + b] = *(float2*)&acc[c8][b];
      }
      __syncthreads();
      if (tid < 64){
        int c8 = tid & 7, bp = tid >> 3;
        int b = bp & 3, bh2 = bp >> 2;
        float vx = 0.f, vy = 0.f;
        #pragma unroll
        for (int q = 0; q < 4; q++){
          float2 p = red[(bh2*4 + q)*32 + c8*4 + b];
          vx += p.x; vy += p.y;
        }
        int j = c*8 + c8, m0 = t*16 + bp*2;
        float n0 = tanhf(vx + Gn[(size_t)m0*SS + j]);
        float n1 = tanhf(vy + Gn[(size_t)(m0+1)*SS + j]);
        float2 z2 = szp[c8*8 + bp];
        float2 ho = g_hf[bp*1024 + j];
        float h0 = ho.x + z2.x*(n0 - ho.x);
        float h1 = ho.y + z2.y*(n1 - ho.y);
        g_hf[bp*1024 + j] = make_float2(h0, h1);
        Hout[(size_t)m0*SS + j]     = h0;
        Hout[(size_t)(m0+1)*SS + j] = h1;
      }
    }
    gsync();
  }
}

// ---------------- h_final tail ----------------------------------------------
__global__ void hfin_k(const float* __restrict__ H1, float* __restrict__ out){
  int i = blockIdx.x*256 + threadIdx.x;   // 0..32767
  int l = i >> 14, rest = i & 16383;
  const float* H = l ? g_H2 : H1;
  out[i] = H[(size_t)(255*16 + (rest >> 10))*SS + (rest & 1023)];
}

// ---------------- launch -----------------------------------------------------
extern "C" void kernel_launch(void* const* d_in, const int* in_sizes, int n_in,
                              void* d_out, int out_size) {
  const int*   x   = (const int*)d_in[0];
  const float* emb = (const float*)d_in[1];
  const float* Wz  = (const float*)d_in[2];
  const float* bz  = (const float*)d_in[3];
  const float* Wr  = (const float*)d_in[4];
  const float* br  = (const float*)d_in[5];
  const float* Wn  = (const float*)d_in[6];
  const float* bn  = (const float*)d_in[7];
  const float* Wo  = (const float*)d_in[8];
  const float* bo  = (const float*)d_in[9];
  float* out = (float*)d_out;

  cudaFuncSetAttribute(gru_layer_k, cudaFuncAttributeMaxDynamicSharedMemorySize, GRU_DSMEM);
  cudaFuncSetAttribute(mgemm_k,     cudaFuncAttributeMaxDynamicSharedMemorySize, MG_SMEM);

  void* pH2v; cudaGetSymbolAddress(&pH2v, g_H2);
  float* H2 = (float*)pH2v;
  void* pHhi; cudaGetSymbolAddress(&pHhi, g_Hhi);
  void* pHlo; cudaGetSymbolAddress(&pHlo, g_Hlo);
  const __nv_bfloat16* Hhi = (const __nv_bfloat16*)pHhi;
  const __nv_bfloat16* Hlo = (const __nv_bfloat16*)pHlo;

  // fp32 scratch inside d_out (dead before the output GEMM writes logits):
  float* Gz_s = out;                       // 16 MB
  float* Gr_s = out + (size_t)(4u<<20);    // 16 MB
  float* Gn_s = out + (size_t)(8u<<20);    // 16 MB
  float* H1   = out + (size_t)(12u<<20);   // 16 MB

  const size_t slab = (size_t)2048 * SS;   // per-layer W* slab ((E+S) x S)
  const size_t MSZ  = (size_t)SS * SS;     // h-part offset within slab

  embed_k<<<MM, 256>>>(x, emb, H2);        // X lives in g_H2 until layer 1
  split_k<<<4096, 256>>>(H2);              // A operand = X

  for (int l = 0; l < 2; l++){
    mgemm_k<<<dim3(32, 8), 256, MG_SMEM>>>(Hhi, Hlo, Wz + l*slab, bz + l*SS, Gz_s, SS, 0);
    mgemm_k<<<dim3(32, 8), 256, MG_SMEM>>>(Hhi, Hlo, Wr + l*slab, br + l*SS, Gr_s, SS, 0);
    mgemm_k<<<dim3(32, 8), 256, MG_SMEM>>>(Hhi, Hlo, Wn + l*slab, bn + l*SS, Gn_s, SS, 0);
    zero_h_k<<<32, 256>>>();
    float* Hout = l ? H2 : H1;
    gru_layer_k<<<RCTAS, 256, GRU_DSMEM>>>(
        Gz_s, Gr_s, Gn_s,
        Wz + l*slab + MSZ, Wr + l*slab + MSZ, Wn + l*slab + MSZ, Hout);
    split_k<<<4096, 256>>>(Hout);          // A operand for next stage
  }

  // h_final first (reads H1 scratch before logits overwrite it)
  hfin_k<<<RCTAS, 256>>>(H1, out + (size_t)MM*VV);

  // output projection: [4096,1024]@[1024,32000] + bo, rows remapped to [B,T]
  mgemm_k<<<dim3(32, 250), 256, MG_SMEM>>>(Hhi, Hlo, Wo, bo, out, VV, 1);
}